// round 8
// baseline (speedup 1.0000x reference)
#include <cuda_runtime.h>
#include <cuda_bf16.h>
#include <cstdint>
#include <math.h>

#define BB 4096
#define TT 200
#define EE 64
#define NPREP 7296          // 4096 attn CTAs + 3200 xp CTAs

using u64 = unsigned long long;

// ---------------- device globals ----------------
__device__ float g_att[(size_t)BB * TT];            // softmax * mask, [B,T]
__device__ float g_xp[3ull * BB * TT * EE];         // xp = gru@W + b, [gate][b*T+t][e]
#define RT64 ((size_t)BB * TT * EE)

// ---------------- packed fp32x2 helpers ----------------
static __device__ __forceinline__ u64 pk2(float x, float y) {
    u64 r; asm("mov.b64 %0,{%1,%2};" : "=l"(r) : "f"(x), "f"(y)); return r;
}
static __device__ __forceinline__ float2 up2(u64 v) {
    float2 r; asm("mov.b64 {%0,%1},%2;" : "=f"(r.x), "=f"(r.y) : "l"(v)); return r;
}
static __device__ __forceinline__ void fma2(u64& d, u64 a, u64 b) {
    asm("fma.rn.f32x2 %0,%1,%2,%0;" : "+l"(d) : "l"(a), "l"(b));
}
static __device__ __forceinline__ float rcpa(float x) {
    float r; asm("rcp.approx.f32 %0, %1;" : "=f"(r) : "f"(x)); return r;
}
// two sigmoids sharing one MUFU.RCP (stable -|x| form; error ~1e-7)
static __device__ __forceinline__ float2 sigmoid2(float a, float b) {
    float ea = __expf(-fabsf(a)), eb = __expf(-fabsf(b));
    float pa = 1.0f + ea, pb = 1.0f + eb;
    float R  = rcpa(pa * pb);
    float ia = pb * R, ib = pa * R;        // 1/pa, 1/pb
    float sa = (a >= 0.0f) ? ia : ea * ia;
    float sb = (b >= 0.0f) ? ib : eb * ib;
    return make_float2(sa, sb);
}
// two tanhs sharing one MUFU.RCP
static __device__ __forceinline__ float2 tanh2(float a, float b) {
    float ea = __expf(-2.0f * fabsf(a)), eb = __expf(-2.0f * fabsf(b));
    float pa = 1.0f + ea, pb = 1.0f + eb;
    float R  = rcpa(pa * pb);
    float ta = (1.0f - ea) * pb * R, tb = (1.0f - eb) * pa * R;
    return make_float2(copysignf(ta, a), copysignf(tb, b));
}
static __device__ __forceinline__ void cp_async16(void* dst, const void* src) {
    unsigned s = (unsigned)__cvta_generic_to_shared(dst);
    asm volatile("cp.async.cg.shared.global [%0], [%1], 16;" :: "r"(s), "l"(src));
}
static __device__ __forceinline__ int load_mask(const void* mp, size_t idx, int u8) {
    return u8 ? (int)(((const unsigned char*)mp)[idx] != 0)
              : (int)(((const int*)mp)[idx] != 0);
}

// =====================================================================
// attn body: logits + softmax (mask folded), one CTA per b. MUFU-heavy.
// =====================================================================
static __device__ void attn_body(
    int b, float* sm,
    const float* __restrict__ gru, const float* __restrict__ query,
    const void* __restrict__ maskp,
    const float* __restrict__ aw1, const float* __restrict__ ab1,
    const float* __restrict__ aw2, const float* __restrict__ ab2,
    const float* __restrict__ aw3, const float* __restrict__ ab3)
{
    float* q_s   = sm;              // 64
    float* qa_s  = sm + 64;         // 32
    float* Wk_s  = sm + 96;         // 64*32 = A1 - A2
    float* Wqk_s = Wk_s + 2048;     // 64*32 = A3
    float* aw2_s = Wqk_s + 2048;    // 512
    float* ab2_s = aw2_s + 512;     // 16
    float* aw3_s = ab2_s + 16;      // 16
    float* red_s = aw3_s + 16;      // 16 (reductions + mask-dtype flag @12)
    float* Ks    = red_s + 16;      // 200*65

    int tid = threadIdx.x;

    if (tid < 32) {   // warp-parallel mask dtype detection
        const unsigned int* mw = (const unsigned int*)maskp;
        unsigned bad = 0;
        #pragma unroll
        for (int i = 0; i < 16; i++) bad |= (mw[tid * 16 + i] > 1u) ? 1u : 0u;
        unsigned any = __any_sync(0xffffffffu, bad);
        if (tid == 0) red_s[12] = any ? 1.0f : 0.0f;
    }

    if (tid < 64) q_s[tid] = query[(size_t)b * EE + tid];
    for (int i = tid; i < 2048; i += 256) {
        int e = i >> 5, j = i & 31;
        Wk_s[i]  = aw1[(64 + e) * 32 + j] - aw1[(128 + e) * 32 + j];
        Wqk_s[i] = aw1[(192 + e) * 32 + j];
    }
    for (int i = tid; i < 512; i += 256) aw2_s[i] = aw2[i];
    if (tid < 16) { ab2_s[tid] = ab2[tid]; aw3_s[tid] = aw3[tid]; }
    for (int i = tid; i < TT * 16; i += 256) {
        int row = i >> 4, c = (i & 15) * 4;
        float4 v = *(const float4*)(gru + ((size_t)b * TT + row) * EE + c);
        float* d = Ks + row * 65 + c;
        d[0] = v.x; d[1] = v.y; d[2] = v.z; d[3] = v.w;
    }
    __syncthreads();

    if (tid < 32) {
        float s = ab1[tid];
        for (int e = 0; e < 64; e++)
            s += q_s[e] * (aw1[e * 32 + tid] + aw1[(128 + e) * 32 + tid]);
        qa_s[tid] = s;
    }
    __syncthreads();

    int mu8 = (red_s[12] != 0.0f);
    int t = tid;
    float lg = -3.0e38f;
    int mflag = 0;
    if (t < TT) {
        u64 acc[16];
        const ulonglong2* Wk4  = (const ulonglong2*)Wk_s;
        const ulonglong2* Wqk4 = (const ulonglong2*)Wqk_s;
        #pragma unroll
        for (int j = 0; j < 16; j++) acc[j] = pk2(qa_s[2 * j], qa_s[2 * j + 1]);
        const float* kr = Ks + t * 65;
        #pragma unroll 4
        for (int e = 0; e < 64; e++) {
            float kv = kr[e];
            float qk = q_s[e] * kv;
            u64 kv2 = pk2(kv, kv), qk2 = pk2(qk, qk);
            #pragma unroll
            for (int j2 = 0; j2 < 8; j2++) {
                ulonglong2 wa = Wk4[e * 8 + j2];
                fma2(acc[2 * j2],     kv2, wa.x);
                fma2(acc[2 * j2 + 1], kv2, wa.y);
                ulonglong2 wb = Wqk4[e * 8 + j2];
                fma2(acc[2 * j2],     qk2, wb.x);
                fma2(acc[2 * j2 + 1], qk2, wb.y);
            }
        }
        u64 acc2[8];
        const ulonglong2* A24 = (const ulonglong2*)aw2_s;
        #pragma unroll
        for (int j = 0; j < 8; j++) acc2[j] = pk2(ab2_s[2 * j], ab2_s[2 * j + 1]);
        #pragma unroll
        for (int j = 0; j < 16; j++) {
            float2 v = up2(acc[j]);
            float2 h = sigmoid2(v.x, v.y);
            u64 ha = pk2(h.x, h.x), hb = pk2(h.y, h.y);
            #pragma unroll
            for (int j2 = 0; j2 < 4; j2++) {
                ulonglong2 wa = A24[(2 * j) * 4 + j2];
                fma2(acc2[2 * j2],     ha, wa.x);
                fma2(acc2[2 * j2 + 1], ha, wa.y);
                ulonglong2 wb = A24[(2 * j + 1) * 4 + j2];
                fma2(acc2[2 * j2],     hb, wb.x);
                fma2(acc2[2 * j2 + 1], hb, wb.y);
            }
        }
        float lgt = ab3[0];
        #pragma unroll
        for (int j = 0; j < 8; j++) {
            float2 v = up2(acc2[j]);
            float2 h = sigmoid2(v.x, v.y);
            lgt += h.x * aw3_s[2 * j] + h.y * aw3_s[2 * j + 1];
        }
        mflag = load_mask(maskp, (size_t)b * TT + t, mu8);
        lg = mflag ? lgt : -1.0e9f;
    }

    float v = lg;
    #pragma unroll
    for (int off = 16; off > 0; off >>= 1) v = fmaxf(v, __shfl_xor_sync(0xffffffffu, v, off));
    if ((tid & 31) == 0) red_s[tid >> 5] = v;
    __syncthreads();
    if (tid == 0) { float m = red_s[0]; for (int i = 1; i < 8; i++) m = fmaxf(m, red_s[i]); red_s[8] = m; }
    __syncthreads();
    float bmax = red_s[8];
    float ex = (t < TT) ? __expf(lg - bmax) : 0.0f;
    float s = ex;
    #pragma unroll
    for (int off = 16; off > 0; off >>= 1) s += __shfl_xor_sync(0xffffffffu, s, off);
    if ((tid & 31) == 0) red_s[tid >> 5] = s;
    __syncthreads();
    if (tid == 0) { float m = 0.0f; for (int i = 0; i < 8; i++) m += red_s[i]; red_s[9] = m; }
    __syncthreads();
    float inv = __frcp_rn(red_s[9]);
    if (t < TT) g_att[(size_t)b * TT + t] = ex * inv * (mflag ? 1.0f : 0.0f);
}

// =====================================================================
// xp body: xp = gru@W + b (gate-split). FMA-heavy. 256 rows/CTA,
// 8 tiles of 32 rows, cp.async double-buffered, warp owns 4 rows/tile.
// =====================================================================
#define XP_RPB 256
static __device__ void xp_body(
    int cb, float* sm,
    const float* __restrict__ gru, const float* __restrict__ W,
    const float* __restrict__ bias)
{
    float* Wr = sm;                 // [64][66] each
    float* Wz = Wr + 64 * 66;
    float* Wn = Wz + 64 * 66;
    float* kS = Wn + 64 * 66;       // [2][32][68]

    int tid = threadIdx.x, lane = tid & 31, wid = tid >> 5;
    size_t row0 = (size_t)cb * XP_RPB;

    for (int i = tid; i < 64 * 64; i += 256) {
        int k = i >> 6, e = i & 63;
        const float* wrow = W + k * 192;
        Wr[k * 66 + e] = wrow[e];
        Wz[k * 66 + e] = wrow[64 + e];
        Wn[k * 66 + e] = wrow[128 + e];
    }

    int r = tid >> 3, c0 = (tid & 7) * 8;
    {   // preload tile 0
        const float* src = gru + (row0 + r) * EE + c0;
        float* dst = kS + r * 68 + c0;
        cp_async16(dst, src); cp_async16(dst + 4, src + 4);
        asm volatile("cp.async.commit_group;");
    }

    u64 br = *(const u64*)(bias + 2 * lane);
    u64 bz = *(const u64*)(bias + 64 + 2 * lane);
    u64 bn = *(const u64*)(bias + 128 + 2 * lane);
    int r0 = wid * 4;

    for (int tile = 0; tile < XP_RPB / 32; tile++) {
        int cur = tile & 1, nxt = cur ^ 1;
        bool more = (tile + 1 < XP_RPB / 32);
        if (more) {
            const float* src = gru + (row0 + (tile + 1) * 32 + r) * EE + c0;
            float* dst = kS + nxt * 2176 + r * 68 + c0;
            cp_async16(dst, src); cp_async16(dst + 4, src + 4);
            asm volatile("cp.async.commit_group;");
            asm volatile("cp.async.wait_group 1;" ::: "memory");
        } else {
            asm volatile("cp.async.wait_group 0;" ::: "memory");
        }
        __syncthreads();

        u64 ar[4], az[4], an[4];
        #pragma unroll
        for (int rr = 0; rr < 4; rr++) { ar[rr] = br; az[rr] = bz; an[rr] = bn; }
        const float* kc = kS + cur * 2176;
        #pragma unroll 2
        for (int k = 0; k < 64; k++) {
            u64 wr = *(const u64*)(Wr + k * 66 + 2 * lane);
            u64 wz = *(const u64*)(Wz + k * 66 + 2 * lane);
            u64 wn = *(const u64*)(Wn + k * 66 + 2 * lane);
            #pragma unroll
            for (int rr = 0; rr < 4; rr++) {
                float kv = kc[(r0 + rr) * 68 + k];
                u64 k2 = pk2(kv, kv);
                fma2(ar[rr], k2, wr); fma2(az[rr], k2, wz); fma2(an[rr], k2, wn);
            }
        }
        #pragma unroll
        for (int rr = 0; rr < 4; rr++) {
            size_t row = row0 + tile * 32 + r0 + rr;
            *(u64*)(g_xp +            row * EE + 2 * lane) = ar[rr];
            *(u64*)(g_xp + RT64     + row * EE + 2 * lane) = az[rr];
            *(u64*)(g_xp + 2 * RT64 + row * EE + 2 * lane) = an[rr];
        }
        __syncthreads();
    }
}

// =====================================================================
// prep: attn + xp fused in one launch, interleaved by bid-swizzle so
// MUFU-bound (attn) and FMA-bound (xp) CTAs co-reside on each SM.
// =====================================================================
__global__ __launch_bounds__(256, 2) void prep_kernel(
    const float* __restrict__ gru, const float* __restrict__ query,
    const void* __restrict__ maskp,
    const float* __restrict__ aw1, const float* __restrict__ ab1,
    const float* __restrict__ aw2, const float* __restrict__ ab2,
    const float* __restrict__ aw3, const float* __restrict__ ab3,
    const float* __restrict__ W, const float* __restrict__ bias)
{
    extern __shared__ float sm[];
    unsigned sid = (blockIdx.x * 5u) % (unsigned)NPREP;   // gcd(5,7296)=1
    if (sid < (unsigned)BB)
        attn_body((int)sid, sm, gru, query, maskp, aw1, ab1, aw2, ab2, aw3, ab3);
    else
        xp_body((int)(sid - BB), sm, gru, W, bias);
}

// =====================================================================
// scan: h@U only (xp precomputed). 128 CTAs x 512 thr (4 warps/SMSP),
// 32 rows/CTA; warp w owns rows {2w, 2w+1}, lane owns e-pair.
// h stored duplicated+paired: hT2[e][4w..4w+3] = {h2w, h2w, h2w+1, h2w+1}
// -> one broadcast LDS.128 per k yields both rows as ready u64 pairs.
// =====================================================================
#define HT2_S 68
__global__ __launch_bounds__(512, 1) void scan_kernel(
    const float* __restrict__ U, float* __restrict__ out)
{
    extern __shared__ float sm[];
    float* Ur = sm;                 // [64][66] each
    float* Uz = Ur + 64 * 66;
    float* Un = Uz + 64 * 66;
    float* hT2  = Un + 64 * 66;     // [64][68]
    float* attS = hT2 + 64 * HT2_S; // [2][32]

    int tid = threadIdx.x, lane = tid & 31, wid = tid >> 5;
    int rb  = blockIdx.x * 32;

    for (int i = tid; i < 64 * 64; i += 512) {
        int k = i >> 6, e = i & 63;
        const float* urow = U + k * 192;
        Ur[k * 66 + e] = urow[e];
        Uz[k * 66 + e] = urow[64 + e];
        Un[k * 66 + e] = urow[128 + e];
    }
    for (int i = tid; i < 64 * HT2_S; i += 512) hT2[i] = 0.0f;
    if (tid < 32) attS[tid] = g_att[(size_t)(rb + tid) * TT];
    __syncthreads();

    int r0 = wid * 2;               // first of this warp's two rows
    float2 hreg[2];
    hreg[0] = make_float2(0.0f, 0.0f);
    hreg[1] = make_float2(0.0f, 0.0f);

    u64 xcr[2], xcz[2], xcn[2];
    #pragma unroll
    for (int rr = 0; rr < 2; rr++) {
        size_t row = ((size_t)(rb + r0 + rr) * TT) * EE + 2 * lane;   // t = 0
        xcr[rr] = *(const u64*)(g_xp + row);
        xcz[rr] = *(const u64*)(g_xp + RT64 + row);
        xcn[rr] = *(const u64*)(g_xp + 2 * RT64 + row);
    }

    for (int t = 0; t < TT; t++) {
        int cur = t & 1, nxt = cur ^ 1;

        u64 xnr[2], xnz[2], xnn[2];
        float aN = 0.0f;
        if (t + 1 < TT) {
            #pragma unroll
            for (int rr = 0; rr < 2; rr++) {
                size_t row = ((size_t)(rb + r0 + rr) * TT + (t + 1)) * EE + 2 * lane;
                xnr[rr] = *(const u64*)(g_xp + row);
                xnz[rr] = *(const u64*)(g_xp + RT64 + row);
                xnn[rr] = *(const u64*)(g_xp + 2 * RT64 + row);
            }
            if (tid < 32) aN = g_att[(size_t)(rb + tid) * TT + t + 1];
        }

        u64 a2r[2] = {0ull, 0ull}, a2z[2] = {0ull, 0ull}, a2n[2] = {0ull, 0ull};

        #pragma unroll 4
        for (int k = 0; k < 64; k++) {
            float4 hq = *(const float4*)(hT2 + k * HT2_S + 4 * wid);  // broadcast
            u64 h2a = ((const u64*)&hq)[0];   // {h_row0, h_row0}
            u64 h2b = ((const u64*)&hq)[1];   // {h_row1, h_row1}
            u64 ur = *(const u64*)(Ur + k * 66 + 2 * lane);
            u64 uz = *(const u64*)(Uz + k * 66 + 2 * lane);
            u64 un = *(const u64*)(Un + k * 66 + 2 * lane);
            fma2(a2r[0], h2a, ur); fma2(a2z[0], h2a, uz); fma2(a2n[0], h2a, un);
            fma2(a2r[1], h2b, ur); fma2(a2z[1], h2b, uz); fma2(a2n[1], h2b, un);
        }

        __syncthreads();   // all warps done reading hT2 of step t

        #pragma unroll
        for (int rr = 0; rr < 2; rr++) {
            int row = r0 + rr;
            float2 xr = up2(xcr[rr]), xz = up2(xcz[rr]), xn = up2(xcn[rr]);
            float2 hr = up2(a2r[rr]), hz = up2(a2z[rr]), hn = up2(a2n[rr]);
            float av = attS[cur * 32 + row];      // mask already folded
            float2 hold = hreg[rr];
            float2 rg = sigmoid2(xr.x + hr.x, xr.y + hr.y);
            float2 zg = sigmoid2(xz.x + hz.x, xz.y + hz.y);
            float2 ng = tanh2(xn.x + rg.x * hn.x, xn.y + rg.y * hn.y);
            float zt0 = av * zg.x, zt1 = av * zg.y;
            hreg[rr] = make_float2(hold.x + zt0 * (ng.x - hold.x),
                                   hold.y + zt1 * (ng.y - hold.y));
        }
        // duplicated transposed write: 2x STS.128
        {
            float4 v0 = make_float4(hreg[0].x, hreg[0].x, hreg[1].x, hreg[1].x);
            float4 v1 = make_float4(hreg[0].y, hreg[0].y, hreg[1].y, hreg[1].y);
            *(float4*)(hT2 + (2 * lane)     * HT2_S + 4 * wid) = v0;
            *(float4*)(hT2 + (2 * lane + 1) * HT2_S + 4 * wid) = v1;
        }
        if (t + 1 < TT) {
            if (tid < 32) attS[nxt * 32 + tid] = aN;
            #pragma unroll
            for (int rr = 0; rr < 2; rr++) {
                xcr[rr] = xnr[rr]; xcz[rr] = xnz[rr]; xcn[rr] = xnn[rr];
            }
        }
        __syncthreads();   // hT2/attS ready for step t+1
    }

    #pragma unroll
    for (int rr = 0; rr < 2; rr++) {
        int row = r0 + rr;
        *(float2*)(out + (size_t)(rb + row) * EE + 2 * lane) = hreg[rr];
    }
}

// =====================================================================
extern "C" void kernel_launch(void* const* d_in, const int* in_sizes, int n_in,
                              void* d_out, int out_size) {
    const float* gru   = (const float*)d_in[0];
    const float* query = (const float*)d_in[1];
    const void*  maskp = (const void*) d_in[2];
    const float* aw1   = (const float*)d_in[3];
    const float* ab1   = (const float*)d_in[4];
    const float* aw2   = (const float*)d_in[5];
    const float* ab2   = (const float*)d_in[6];
    const float* aw3   = (const float*)d_in[7];
    const float* ab3   = (const float*)d_in[8];
    const float* W     = (const float*)d_in[9];
    const float* U     = (const float*)d_in[10];
    const float* bias  = (const float*)d_in[11];
    float* out = (float*)d_out;

    const int attn_sz  = (64 + 32 + 2048 + 2048 + 512 + 16 + 16 + 16 + TT * 65) * 4;
    const int xp_sz    = (3 * 64 * 66 + 2 * 32 * 68) * 4;
    const int prep_smem = attn_sz > xp_sz ? attn_sz : xp_sz;
    const int scan_smem = (3 * 64 * 66 + 64 * HT2_S + 64) * 4;
    cudaFuncSetAttribute(prep_kernel, cudaFuncAttributeMaxDynamicSharedMemorySize, prep_smem);
    cudaFuncSetAttribute(scan_kernel, cudaFuncAttributeMaxDynamicSharedMemorySize, scan_smem);

    prep_kernel<<<NPREP, 256, prep_smem>>>(gru, query, maskp,
                                           aw1, ab1, aw2, ab2, aw3, ab3, W, bias);
    scan_kernel<<<128, 512, scan_smem>>>(U, out);
}

// round 9
// speedup vs baseline: 1.2132x; 1.2132x over previous
#include <cuda_runtime.h>
#include <cuda_bf16.h>
#include <cstdint>
#include <math.h>

#define BB 4096
#define TT 200
#define EE 64

using u64 = unsigned long long;

// ---------------- device globals ----------------
__device__ float g_att[(size_t)BB * TT];            // softmax * mask, [B,T]
__device__ float g_xp[3ull * BB * TT * EE];         // xp = gru@W + b, [gate][b*T+t][e]
#define RT64 ((size_t)BB * TT * EE)

// ---------------- packed fp32x2 helpers ----------------
static __device__ __forceinline__ u64 pk2(float x, float y) {
    u64 r; asm("mov.b64 %0,{%1,%2};" : "=l"(r) : "f"(x), "f"(y)); return r;
}
static __device__ __forceinline__ float2 up2(u64 v) {
    float2 r; asm("mov.b64 {%0,%1},%2;" : "=f"(r.x), "=f"(r.y) : "l"(v)); return r;
}
static __device__ __forceinline__ void fma2(u64& d, u64 a, u64 b) {
    asm("fma.rn.f32x2 %0,%1,%2,%0;" : "+l"(d) : "l"(a), "l"(b));
}
static __device__ __forceinline__ float rcpa(float x) {
    float r; asm("rcp.approx.f32 %0, %1;" : "=f"(r) : "f"(x)); return r;
}
// two sigmoids sharing one MUFU.RCP (validated R8: rel_err 3.3e-7)
static __device__ __forceinline__ float2 sigmoid2(float a, float b) {
    float ea = __expf(-fabsf(a)), eb = __expf(-fabsf(b));
    float pa = 1.0f + ea, pb = 1.0f + eb;
    float R  = rcpa(pa * pb);
    float ia = pb * R, ib = pa * R;
    float sa = (a >= 0.0f) ? ia : ea * ia;
    float sb = (b >= 0.0f) ? ib : eb * ib;
    return make_float2(sa, sb);
}
// two tanhs sharing one MUFU.RCP (validated R8)
static __device__ __forceinline__ float2 tanh2(float a, float b) {
    float ea = __expf(-2.0f * fabsf(a)), eb = __expf(-2.0f * fabsf(b));
    float pa = 1.0f + ea, pb = 1.0f + eb;
    float R  = rcpa(pa * pb);
    float ta = (1.0f - ea) * pb * R, tb = (1.0f - eb) * pa * R;
    return make_float2(copysignf(ta, a), copysignf(tb, b));
}
static __device__ __forceinline__ void cp_async16(void* dst, const void* src) {
    unsigned s = (unsigned)__cvta_generic_to_shared(dst);
    asm volatile("cp.async.cg.shared.global [%0], [%1], 16;" :: "r"(s), "l"(src));
}
static __device__ __forceinline__ int load_mask(const void* mp, size_t idx, int u8) {
    return u8 ? (int)(((const unsigned char*)mp)[idx] != 0)
              : (int)(((const int*)mp)[idx] != 0);
}

// =====================================================================
// Kernel 1: attention logits + softmax (mask folded), one CTA per b.
// =====================================================================
__global__ __launch_bounds__(256, 2) void attn_kernel(
    const float* __restrict__ gru, const float* __restrict__ query,
    const void* __restrict__ maskp,
    const float* __restrict__ aw1, const float* __restrict__ ab1,
    const float* __restrict__ aw2, const float* __restrict__ ab2,
    const float* __restrict__ aw3, const float* __restrict__ ab3)
{
    extern __shared__ float sm[];
    float* q_s   = sm;              // 64
    float* qa_s  = sm + 64;         // 32
    float* Wk_s  = sm + 96;         // 64*32 = A1 - A2
    float* Wqk_s = Wk_s + 2048;     // 64*32 = A3
    float* aw2_s = Wqk_s + 2048;    // 512
    float* ab2_s = aw2_s + 512;     // 16
    float* aw3_s = ab2_s + 16;      // 16
    float* red_s = aw3_s + 16;      // 16 (reductions + mask-dtype flag @12)
    float* Ks    = red_s + 16;      // 200*65

    int tid = threadIdx.x;
    int b   = blockIdx.x;

    if (tid < 32) {   // warp-parallel mask dtype detection
        const unsigned int* mw = (const unsigned int*)maskp;
        unsigned bad = 0;
        #pragma unroll
        for (int i = 0; i < 16; i++) bad |= (mw[tid * 16 + i] > 1u) ? 1u : 0u;
        unsigned any = __any_sync(0xffffffffu, bad);
        if (tid == 0) red_s[12] = any ? 1.0f : 0.0f;
    }

    if (tid < 64) q_s[tid] = query[(size_t)b * EE + tid];
    for (int i = tid; i < 2048; i += 256) {
        int e = i >> 5, j = i & 31;
        Wk_s[i]  = aw1[(64 + e) * 32 + j] - aw1[(128 + e) * 32 + j];
        Wqk_s[i] = aw1[(192 + e) * 32 + j];
    }
    for (int i = tid; i < 512; i += 256) aw2_s[i] = aw2[i];
    if (tid < 16) { ab2_s[tid] = ab2[tid]; aw3_s[tid] = aw3[tid]; }
    for (int i = tid; i < TT * 16; i += 256) {
        int row = i >> 4, c = (i & 15) * 4;
        float4 v = *(const float4*)(gru + ((size_t)b * TT + row) * EE + c);
        float* d = Ks + row * 65 + c;
        d[0] = v.x; d[1] = v.y; d[2] = v.z; d[3] = v.w;
    }
    __syncthreads();

    if (tid < 32) {
        float s = ab1[tid];
        for (int e = 0; e < 64; e++)
            s += q_s[e] * (aw1[e * 32 + tid] + aw1[(128 + e) * 32 + tid]);
        qa_s[tid] = s;
    }
    __syncthreads();

    int mu8 = (red_s[12] != 0.0f);
    int t = tid;
    float lg = -3.0e38f;
    int mflag = 0;
    if (t < TT) {
        u64 acc[16];
        const ulonglong2* Wk4  = (const ulonglong2*)Wk_s;
        const ulonglong2* Wqk4 = (const ulonglong2*)Wqk_s;
        #pragma unroll
        for (int j = 0; j < 16; j++) acc[j] = pk2(qa_s[2 * j], qa_s[2 * j + 1]);
        const float* kr = Ks + t * 65;
        #pragma unroll 4
        for (int e = 0; e < 64; e++) {
            float kv = kr[e];
            float qk = q_s[e] * kv;
            u64 kv2 = pk2(kv, kv), qk2 = pk2(qk, qk);
            #pragma unroll
            for (int j2 = 0; j2 < 8; j2++) {
                ulonglong2 wa = Wk4[e * 8 + j2];
                fma2(acc[2 * j2],     kv2, wa.x);
                fma2(acc[2 * j2 + 1], kv2, wa.y);
                ulonglong2 wb = Wqk4[e * 8 + j2];
                fma2(acc[2 * j2],     qk2, wb.x);
                fma2(acc[2 * j2 + 1], qk2, wb.y);
            }
        }
        u64 acc2[8];
        const ulonglong2* A24 = (const ulonglong2*)aw2_s;
        #pragma unroll
        for (int j = 0; j < 8; j++) acc2[j] = pk2(ab2_s[2 * j], ab2_s[2 * j + 1]);
        #pragma unroll
        for (int j = 0; j < 16; j++) {
            float2 v = up2(acc[j]);
            float2 h = sigmoid2(v.x, v.y);
            u64 ha = pk2(h.x, h.x), hb = pk2(h.y, h.y);
            #pragma unroll
            for (int j2 = 0; j2 < 4; j2++) {
                ulonglong2 wa = A24[(2 * j) * 4 + j2];
                fma2(acc2[2 * j2],     ha, wa.x);
                fma2(acc2[2 * j2 + 1], ha, wa.y);
                ulonglong2 wb = A24[(2 * j + 1) * 4 + j2];
                fma2(acc2[2 * j2],     hb, wb.x);
                fma2(acc2[2 * j2 + 1], hb, wb.y);
            }
        }
        float lgt = ab3[0];
        #pragma unroll
        for (int j = 0; j < 8; j++) {
            float2 v = up2(acc2[j]);
            float2 h = sigmoid2(v.x, v.y);
            lgt += h.x * aw3_s[2 * j] + h.y * aw3_s[2 * j + 1];
        }
        mflag = load_mask(maskp, (size_t)b * TT + t, mu8);
        lg = mflag ? lgt : -1.0e9f;
    }

    float v = lg;
    #pragma unroll
    for (int off = 16; off > 0; off >>= 1) v = fmaxf(v, __shfl_xor_sync(0xffffffffu, v, off));
    if ((tid & 31) == 0) red_s[tid >> 5] = v;
    __syncthreads();
    if (tid == 0) { float m = red_s[0]; for (int i = 1; i < 8; i++) m = fmaxf(m, red_s[i]); red_s[8] = m; }
    __syncthreads();
    float bmax = red_s[8];
    float ex = (t < TT) ? __expf(lg - bmax) : 0.0f;
    float s = ex;
    #pragma unroll
    for (int off = 16; off > 0; off >>= 1) s += __shfl_xor_sync(0xffffffffu, s, off);
    if ((tid & 31) == 0) red_s[tid >> 5] = s;
    __syncthreads();
    if (tid == 0) { float m = 0.0f; for (int i = 0; i < 8; i++) m += red_s[i]; red_s[9] = m; }
    __syncthreads();
    float inv = __frcp_rn(red_s[9]);
    if (t < TT) g_att[(size_t)b * TT + t] = ex * inv * (mflag ? 1.0f : 0.0f);
}

// =====================================================================
// Kernel 2: xp = gru@W + b (gate-split). 128 thr, 8 tiles of 32 rows.
// k-tiles transposed into kT so activation reads are broadcast LDS.128.
// Pipeline: wait(stage) -> transpose stage->kT -> barrier -> issue next
// cp.async into stage (free) -> compute from kT.
// =====================================================================
#define XP_RPB 256
#define KT_S 36
__global__ __launch_bounds__(128) void xp_kernel(
    const float* __restrict__ gru, const float* __restrict__ W,
    const float* __restrict__ bias)
{
    extern __shared__ float sm[];
    float* Wr = sm;                 // [64][66] each
    float* Wz = Wr + 64 * 66;
    float* Wn = Wz + 64 * 66;
    float* stage = Wn + 64 * 66;    // [32][68] cp.async target
    float* kT    = stage + 32 * 68; // [64][36] transposed tile

    int tid = threadIdx.x, lane = tid & 31, wid = tid >> 5;
    size_t row0 = (size_t)blockIdx.x * XP_RPB;

    for (int i = tid; i < 64 * 64; i += 128) {
        int k = i >> 6, e = i & 63;
        const float* wrow = W + k * 192;
        Wr[k * 66 + e] = wrow[e];
        Wz[k * 66 + e] = wrow[64 + e];
        Wn[k * 66 + e] = wrow[128 + e];
    }

    int r = tid >> 2, c0 = (tid & 3) * 16;
    {   // preload tile 0 -> stage
        const float* src = gru + (row0 + r) * EE + c0;
        float* dst = stage + r * 68 + c0;
        cp_async16(dst, src);      cp_async16(dst + 4, src + 4);
        cp_async16(dst + 8, src + 8); cp_async16(dst + 12, src + 12);
        asm volatile("cp.async.commit_group;");
    }

    u64 br = *(const u64*)(bias + 2 * lane);
    u64 bz = *(const u64*)(bias + 64 + 2 * lane);
    u64 bn = *(const u64*)(bias + 128 + 2 * lane);
    int r0 = wid * 8;

    for (int tile = 0; tile < XP_RPB / 32; tile++) {
        asm volatile("cp.async.wait_group 0;" ::: "memory");
        __syncthreads();           // stage holds tile (all threads' copies)

        // transpose stage -> kT
        {
            const float* srow = stage + r * 68 + c0;
            #pragma unroll
            for (int q = 0; q < 4; q++) {
                float4 v = *(const float4*)(srow + 4 * q);
                kT[(c0 + 4 * q + 0) * KT_S + r] = v.x;
                kT[(c0 + 4 * q + 1) * KT_S + r] = v.y;
                kT[(c0 + 4 * q + 2) * KT_S + r] = v.z;
                kT[(c0 + 4 * q + 3) * KT_S + r] = v.w;
            }
        }
        __syncthreads();           // kT ready; stage free

        if (tile + 1 < XP_RPB / 32) {
            const float* src = gru + (row0 + (tile + 1) * 32 + r) * EE + c0;
            float* dst = stage + r * 68 + c0;
            cp_async16(dst, src);      cp_async16(dst + 4, src + 4);
            cp_async16(dst + 8, src + 8); cp_async16(dst + 12, src + 12);
            asm volatile("cp.async.commit_group;");
        }

        u64 ar[8], az[8], an[8];
        #pragma unroll
        for (int rr = 0; rr < 8; rr++) { ar[rr] = br; az[rr] = bz; an[rr] = bn; }
        #pragma unroll 2
        for (int k = 0; k < 64; k++) {
            float4 k03 = *(const float4*)(kT + k * KT_S + r0);      // broadcast
            float4 k47 = *(const float4*)(kT + k * KT_S + r0 + 4);  // broadcast
            u64 wr = *(const u64*)(Wr + k * 66 + 2 * lane);
            u64 wz = *(const u64*)(Wz + k * 66 + 2 * lane);
            u64 wn = *(const u64*)(Wn + k * 66 + 2 * lane);
            float kv8[8] = {k03.x, k03.y, k03.z, k03.w, k47.x, k47.y, k47.z, k47.w};
            #pragma unroll
            for (int rr = 0; rr < 8; rr++) {
                u64 k2 = pk2(kv8[rr], kv8[rr]);
                fma2(ar[rr], k2, wr); fma2(az[rr], k2, wz); fma2(an[rr], k2, wn);
            }
        }
        #pragma unroll
        for (int rr = 0; rr < 8; rr++) {
            size_t row = row0 + tile * 32 + r0 + rr;
            *(u64*)(g_xp +            row * EE + 2 * lane) = ar[rr];
            *(u64*)(g_xp + RT64     + row * EE + 2 * lane) = az[rr];
            *(u64*)(g_xp + 2 * RT64 + row * EE + 2 * lane) = an[rr];
        }
        // next iteration's wait+barrier protects kT reuse
    }
}

// =====================================================================
// Kernel 3: GRU scan (h@U only). 128 CTAs x 256 thr, 8 warps x 4 rows
// (crossbar-optimal warp count), hT transposed [e][row] stride 36.
// =====================================================================
#define HT_S 36
__global__ __launch_bounds__(256, 1) void scan_kernel(
    const float* __restrict__ U, float* __restrict__ out)
{
    extern __shared__ float sm[];
    float* Ur = sm;                 // [64][66] each
    float* Uz = Ur + 64 * 66;
    float* Un = Uz + 64 * 66;
    float* hT   = Un + 64 * 66;     // [64][36]
    float* attS = hT + 64 * HT_S;   // [2][32]

    int tid = threadIdx.x, lane = tid & 31, wid = tid >> 5;
    int rb  = blockIdx.x * 32;

    for (int i = tid; i < 64 * 64; i += 256) {
        int k = i >> 6, e = i & 63;
        const float* urow = U + k * 192;
        Ur[k * 66 + e] = urow[e];
        Uz[k * 66 + e] = urow[64 + e];
        Un[k * 66 + e] = urow[128 + e];
    }
    for (int i = tid; i < 64 * HT_S; i += 256) hT[i] = 0.0f;
    if (tid < 32) attS[tid] = g_att[(size_t)(rb + tid) * TT];
    __syncthreads();

    int r0 = wid * 4;
    float2 hreg[4];
    #pragma unroll
    for (int rr = 0; rr < 4; rr++) hreg[rr] = make_float2(0.0f, 0.0f);

    u64 xcr[4], xcz[4], xcn[4];
    #pragma unroll
    for (int rr = 0; rr < 4; rr++) {
        size_t row = ((size_t)(rb + r0 + rr) * TT) * EE + 2 * lane;   // t = 0
        xcr[rr] = *(const u64*)(g_xp + row);
        xcz[rr] = *(const u64*)(g_xp + RT64 + row);
        xcn[rr] = *(const u64*)(g_xp + 2 * RT64 + row);
    }

    for (int t = 0; t < TT; t++) {
        int cur = t & 1, nxt = cur ^ 1;

        u64 xnr[4], xnz[4], xnn[4];
        float aN = 0.0f;
        if (t + 1 < TT) {
            #pragma unroll
            for (int rr = 0; rr < 4; rr++) {
                size_t row = ((size_t)(rb + r0 + rr) * TT + (t + 1)) * EE + 2 * lane;
                xnr[rr] = *(const u64*)(g_xp + row);
                xnz[rr] = *(const u64*)(g_xp + RT64 + row);
                xnn[rr] = *(const u64*)(g_xp + 2 * RT64 + row);
            }
            if (tid < 32) aN = g_att[(size_t)(rb + tid) * TT + t + 1];
        }

        u64 a2r[4], a2z[4], a2n[4];
        #pragma unroll
        for (int rr = 0; rr < 4; rr++) { a2r[rr] = 0ull; a2z[rr] = 0ull; a2n[rr] = 0ull; }

        #pragma unroll 4
        for (int k = 0; k < 64; k++) {
            float4 h03 = *(const float4*)(hT + k * HT_S + r0);   // broadcast LDS.128
            u64 ur = *(const u64*)(Ur + k * 66 + 2 * lane);
            u64 uz = *(const u64*)(Uz + k * 66 + 2 * lane);
            u64 un = *(const u64*)(Un + k * 66 + 2 * lane);
            float hv4[4] = {h03.x, h03.y, h03.z, h03.w};
            #pragma unroll
            for (int rr = 0; rr < 4; rr++) {
                u64 h2 = pk2(hv4[rr], hv4[rr]);
                fma2(a2r[rr], h2, ur); fma2(a2z[rr], h2, uz); fma2(a2n[rr], h2, un);
            }
        }

        __syncthreads();   // all warps done reading hT of step t

        #pragma unroll
        for (int rr = 0; rr < 4; rr++) {
            int row = r0 + rr;
            float2 xr = up2(xcr[rr]), xz = up2(xcz[rr]), xn = up2(xcn[rr]);
            float2 hr = up2(a2r[rr]), hz = up2(a2z[rr]), hn = up2(a2n[rr]);
            float av = attS[cur * 32 + row];      // mask already folded
            float2 hold = hreg[rr];
            float2 rg = sigmoid2(xr.x + hr.x, xr.y + hr.y);
            float2 zg = sigmoid2(xz.x + hz.x, xz.y + hz.y);
            float2 ng = tanh2(xn.x + rg.x * hn.x, xn.y + rg.y * hn.y);
            float zt0 = av * zg.x, zt1 = av * zg.y;
            hreg[rr] = make_float2(hold.x + zt0 * (ng.x - hold.x),
                                   hold.y + zt1 * (ng.y - hold.y));
        }
        // transposed write: thread owns all 4 rows of its e-pair -> 2x STS.128
        {
            float4 vx = make_float4(hreg[0].x, hreg[1].x, hreg[2].x, hreg[3].x);
            float4 vy = make_float4(hreg[0].y, hreg[1].y, hreg[2].y, hreg[3].y);
            *(float4*)(hT + (2 * lane)     * HT_S + r0) = vx;
            *(float4*)(hT + (2 * lane + 1) * HT_S + r0) = vy;
        }
        if (t + 1 < TT) {
            if (tid < 32) attS[nxt * 32 + tid] = aN;
            #pragma unroll
            for (int rr = 0; rr < 4; rr++) {
                xcr[rr] = xnr[rr]; xcz[rr] = xnz[rr]; xcn[rr] = xnn[rr];
            }
        }
        __syncthreads();   // hT/attS ready for step t+1
    }

    #pragma unroll
    for (int rr = 0; rr < 4; rr++) {
        int row = r0 + rr;
        *(float2*)(out + (size_t)(rb + row) * EE + 2 * lane) = hreg[rr];
    }
}

// =====================================================================
extern "C" void kernel_launch(void* const* d_in, const int* in_sizes, int n_in,
                              void* d_out, int out_size) {
    const float* gru   = (const float*)d_in[0];
    const float* query = (const float*)d_in[1];
    const void*  maskp = (const void*) d_in[2];
    const float* aw1   = (const float*)d_in[3];
    const float* ab1   = (const float*)d_in[4];
    const float* aw2   = (const float*)d_in[5];
    const float* ab2   = (const float*)d_in[6];
    const float* aw3   = (const float*)d_in[7];
    const float* ab3   = (const float*)d_in[8];
    const float* W     = (const float*)d_in[9];
    const float* U     = (const float*)d_in[10];
    const float* bias  = (const float*)d_in[11];
    float* out = (float*)d_out;

    const int attn_smem = (64 + 32 + 2048 + 2048 + 512 + 16 + 16 + 16 + TT * 65) * 4;
    const int xp_smem   = (3 * 64 * 66 + 32 * 68 + 64 * KT_S) * 4;
    const int scan_smem = (3 * 64 * 66 + 64 * HT_S + 64) * 4;
    cudaFuncSetAttribute(attn_kernel, cudaFuncAttributeMaxDynamicSharedMemorySize, attn_smem);
    cudaFuncSetAttribute(xp_kernel,   cudaFuncAttributeMaxDynamicSharedMemorySize, xp_smem);
    cudaFuncSetAttribute(scan_kernel, cudaFuncAttributeMaxDynamicSharedMemorySize, scan_smem);

    attn_kernel<<<BB, 256, attn_smem>>>(gru, query, maskp, aw1, ab1, aw2, ab2, aw3, ab3);
    xp_kernel<<<(BB * TT) / XP_RPB, 128, xp_smem>>>(gru, W, bias);
    scan_kernel<<<128, 256, scan_smem>>>(U, out);
}

// round 11
// speedup vs baseline: 1.2185x; 1.0044x over previous
#include <cuda_runtime.h>
#include <cuda_bf16.h>
#include <cstdint>
#include <math.h>

#define BB 4096
#define TT 200
#define EE 64

using u64 = unsigned long long;

// ---------------- device globals ----------------
__device__ float g_att[(size_t)BB * TT];            // softmax * mask, [B,T]
__device__ float g_xp[3ull * BB * TT * EE];         // xp = gru@W + b, [gate][b*T+t][e]
#define RT64 ((size_t)BB * TT * EE)

// ---------------- packed fp32x2 helpers ----------------
static __device__ __forceinline__ u64 pk2(float x, float y) {
    u64 r; asm("mov.b64 %0,{%1,%2};" : "=l"(r) : "f"(x), "f"(y)); return r;
}
static __device__ __forceinline__ float2 up2(u64 v) {
    float2 r; asm("mov.b64 {%0,%1},%2;" : "=f"(r.x), "=f"(r.y) : "l"(v)); return r;
}
static __device__ __forceinline__ void fma2(u64& d, u64 a, u64 b) {
    asm("fma.rn.f32x2 %0,%1,%2,%0;" : "+l"(d) : "l"(a), "l"(b));
}
static __device__ __forceinline__ float rcpa(float x) {
    float r; asm("rcp.approx.f32 %0, %1;" : "=f"(r) : "f"(x)); return r;
}
// two sigmoids sharing one MUFU.RCP (validated: rel_err 3.3e-7)
static __device__ __forceinline__ float2 sigmoid2(float a, float b) {
    float ea = __expf(-fabsf(a)), eb = __expf(-fabsf(b));
    float pa = 1.0f + ea, pb = 1.0f + eb;
    float R  = rcpa(pa * pb);
    float ia = pb * R, ib = pa * R;
    float sa = (a >= 0.0f) ? ia : ea * ia;
    float sb = (b >= 0.0f) ? ib : eb * ib;
    return make_float2(sa, sb);
}
// two tanhs sharing one MUFU.RCP (validated)
static __device__ __forceinline__ float2 tanh2(float a, float b) {
    float ea = __expf(-2.0f * fabsf(a)), eb = __expf(-2.0f * fabsf(b));
    float pa = 1.0f + ea, pb = 1.0f + eb;
    float R  = rcpa(pa * pb);
    float ta = (1.0f - ea) * pb * R, tb = (1.0f - eb) * pa * R;
    return make_float2(copysignf(ta, a), copysignf(tb, b));
}
static __device__ __forceinline__ void cp_async16(void* dst, const void* src) {
    unsigned s = (unsigned)__cvta_generic_to_shared(dst);
    asm volatile("cp.async.cg.shared.global [%0], [%1], 16;" :: "r"(s), "l"(src));
}
static __device__ __forceinline__ int load_mask(const void* mp, size_t idx, int u8) {
    return u8 ? (int)(((const unsigned char*)mp)[idx] != 0)
              : (int)(((const int*)mp)[idx] != 0);
}

// =====================================================================
// Kernel 1: attention logits + softmax (mask folded), one CTA per b.
// =====================================================================
__global__ __launch_bounds__(256, 2) void attn_kernel(
    const float* __restrict__ gru, const float* __restrict__ query,
    const void* __restrict__ maskp,
    const float* __restrict__ aw1, const float* __restrict__ ab1,
    const float* __restrict__ aw2, const float* __restrict__ ab2,
    const float* __restrict__ aw3, const float* __restrict__ ab3)
{
    extern __shared__ float sm[];
    float* q_s   = sm;              // 64
    float* qa_s  = sm + 64;         // 32
    float* Wk_s  = sm + 96;         // 64*32 = A1 - A2
    float* Wqk_s = Wk_s + 2048;     // 64*32 = A3
    float* aw2_s = Wqk_s + 2048;    // 512
    float* ab2_s = aw2_s + 512;     // 16
    float* aw3_s = ab2_s + 16;      // 16
    float* red_s = aw3_s + 16;      // 16 (reductions + mask-dtype flag @12)
    float* Ks    = red_s + 16;      // 200*65

    int tid = threadIdx.x;
    int b   = blockIdx.x;

    if (tid < 32) {   // warp-parallel mask dtype detection
        const unsigned int* mw = (const unsigned int*)maskp;
        unsigned bad = 0;
        #pragma unroll
        for (int i = 0; i < 16; i++) bad |= (mw[tid * 16 + i] > 1u) ? 1u : 0u;
        unsigned any = __any_sync(0xffffffffu, bad);
        if (tid == 0) red_s[12] = any ? 1.0f : 0.0f;
    }

    if (tid < 64) q_s[tid] = query[(size_t)b * EE + tid];
    for (int i = tid; i < 2048; i += 256) {
        int e = i >> 5, j = i & 31;
        Wk_s[i]  = aw1[(64 + e) * 32 + j] - aw1[(128 + e) * 32 + j];
        Wqk_s[i] = aw1[(192 + e) * 32 + j];
    }
    for (int i = tid; i < 512; i += 256) aw2_s[i] = aw2[i];
    if (tid < 16) { ab2_s[tid] = ab2[tid]; aw3_s[tid] = aw3[tid]; }
    for (int i = tid; i < TT * 16; i += 256) {
        int row = i >> 4, c = (i & 15) * 4;
        float4 v = *(const float4*)(gru + ((size_t)b * TT + row) * EE + c);
        float* d = Ks + row * 65 + c;
        d[0] = v.x; d[1] = v.y; d[2] = v.z; d[3] = v.w;
    }
    __syncthreads();

    if (tid < 32) {
        float s = ab1[tid];
        for (int e = 0; e < 64; e++)
            s += q_s[e] * (aw1[e * 32 + tid] + aw1[(128 + e) * 32 + tid]);
        qa_s[tid] = s;
    }
    __syncthreads();

    int mu8 = (red_s[12] != 0.0f);
    int t = tid;
    float lg = -3.0e38f;
    int mflag = 0;
    if (t < TT) {
        u64 acc[16];
        const ulonglong2* Wk4  = (const ulonglong2*)Wk_s;
        const ulonglong2* Wqk4 = (const ulonglong2*)Wqk_s;
        #pragma unroll
        for (int j = 0; j < 16; j++) acc[j] = pk2(qa_s[2 * j], qa_s[2 * j + 1]);
        const float* kr = Ks + t * 65;
        #pragma unroll 4
        for (int e = 0; e < 64; e++) {
            float kv = kr[e];
            float qk = q_s[e] * kv;
            u64 kv2 = pk2(kv, kv), qk2 = pk2(qk, qk);
            #pragma unroll
            for (int j2 = 0; j2 < 8; j2++) {
                ulonglong2 wa = Wk4[e * 8 + j2];
                fma2(acc[2 * j2],     kv2, wa.x);
                fma2(acc[2 * j2 + 1], kv2, wa.y);
                ulonglong2 wb = Wqk4[e * 8 + j2];
                fma2(acc[2 * j2],     qk2, wb.x);
                fma2(acc[2 * j2 + 1], qk2, wb.y);
            }
        }
        u64 acc2[8];
        const ulonglong2* A24 = (const ulonglong2*)aw2_s;
        #pragma unroll
        for (int j = 0; j < 8; j++) acc2[j] = pk2(ab2_s[2 * j], ab2_s[2 * j + 1]);
        #pragma unroll
        for (int j = 0; j < 16; j++) {
            float2 v = up2(acc[j]);
            float2 h = sigmoid2(v.x, v.y);
            u64 ha = pk2(h.x, h.x), hb = pk2(h.y, h.y);
            #pragma unroll
            for (int j2 = 0; j2 < 4; j2++) {
                ulonglong2 wa = A24[(2 * j) * 4 + j2];
                fma2(acc2[2 * j2],     ha, wa.x);
                fma2(acc2[2 * j2 + 1], ha, wa.y);
                ulonglong2 wb = A24[(2 * j + 1) * 4 + j2];
                fma2(acc2[2 * j2],     hb, wb.x);
                fma2(acc2[2 * j2 + 1], hb, wb.y);
            }
        }
        float lgt = ab3[0];
        #pragma unroll
        for (int j = 0; j < 8; j++) {
            float2 v = up2(acc2[j]);
            float2 h = sigmoid2(v.x, v.y);
            lgt += h.x * aw3_s[2 * j] + h.y * aw3_s[2 * j + 1];
        }
        mflag = load_mask(maskp, (size_t)b * TT + t, mu8);
        lg = mflag ? lgt : -1.0e9f;
    }

    float v = lg;
    #pragma unroll
    for (int off = 16; off > 0; off >>= 1) v = fmaxf(v, __shfl_xor_sync(0xffffffffu, v, off));
    if ((tid & 31) == 0) red_s[tid >> 5] = v;
    __syncthreads();
    if (tid == 0) { float m = red_s[0]; for (int i = 1; i < 8; i++) m = fmaxf(m, red_s[i]); red_s[8] = m; }
    __syncthreads();
    float bmax = red_s[8];
    float ex = (t < TT) ? __expf(lg - bmax) : 0.0f;
    float s = ex;
    #pragma unroll
    for (int off = 16; off > 0; off >>= 1) s += __shfl_xor_sync(0xffffffffu, s, off);
    if ((tid & 31) == 0) red_s[tid >> 5] = s;
    __syncthreads();
    if (tid == 0) { float m = 0.0f; for (int i = 0; i < 8; i++) m += red_s[i]; red_s[9] = m; }
    __syncthreads();
    float inv = __frcp_rn(red_s[9]);
    if (t < TT) g_att[(size_t)b * TT + t] = ex * inv * (mflag ? 1.0f : 0.0f);
}

// =====================================================================
// Kernel 2: xp = gru@W + b (gate-split). 128 thr, 8 tiles of 32 rows.
// k-tiles transposed into kT so activation reads are broadcast LDS.128.
// =====================================================================
#define XP_RPB 256
#define KT_S 36
__global__ __launch_bounds__(128) void xp_kernel(
    const float* __restrict__ gru, const float* __restrict__ W,
    const float* __restrict__ bias)
{
    extern __shared__ float sm[];
    float* Wr = sm;                 // [64][66] each
    float* Wz = Wr + 64 * 66;
    float* Wn = Wz + 64 * 66;
    float* stage = Wn + 64 * 66;    // [32][68] cp.async target
    float* kT    = stage + 32 * 68; // [64][36] transposed tile

    int tid = threadIdx.x, lane = tid & 31, wid = tid >> 5;
    size_t row0 = (size_t)blockIdx.x * XP_RPB;

    for (int i = tid; i < 64 * 64; i += 128) {
        int k = i >> 6, e = i & 63;
        const float* wrow = W + k * 192;
        Wr[k * 66 + e] = wrow[e];
        Wz[k * 66 + e] = wrow[64 + e];
        Wn[k * 66 + e] = wrow[128 + e];
    }

    int r = tid >> 2, c0 = (tid & 3) * 16;
    {   // preload tile 0 -> stage
        const float* src = gru + (row0 + r) * EE + c0;
        float* dst = stage + r * 68 + c0;
        cp_async16(dst, src);      cp_async16(dst + 4, src + 4);
        cp_async16(dst + 8, src + 8); cp_async16(dst + 12, src + 12);
        asm volatile("cp.async.commit_group;");
    }

    u64 br = *(const u64*)(bias + 2 * lane);
    u64 bz = *(const u64*)(bias + 64 + 2 * lane);
    u64 bn = *(const u64*)(bias + 128 + 2 * lane);
    int r0 = wid * 8;

    for (int tile = 0; tile < XP_RPB / 32; tile++) {
        asm volatile("cp.async.wait_group 0;" ::: "memory");
        __syncthreads();           // stage holds tile

        {   // transpose stage -> kT
            const float* srow = stage + r * 68 + c0;
            #pragma unroll
            for (int q = 0; q < 4; q++) {
                float4 v = *(const float4*)(srow + 4 * q);
                kT[(c0 + 4 * q + 0) * KT_S + r] = v.x;
                kT[(c0 + 4 * q + 1) * KT_S + r] = v.y;
                kT[(c0 + 4 * q + 2) * KT_S + r] = v.z;
                kT[(c0 + 4 * q + 3) * KT_S + r] = v.w;
            }
        }
        __syncthreads();           // kT ready; stage free

        if (tile + 1 < XP_RPB / 32) {
            const float* src = gru + (row0 + (tile + 1) * 32 + r) * EE + c0;
            float* dst = stage + r * 68 + c0;
            cp_async16(dst, src);      cp_async16(dst + 4, src + 4);
            cp_async16(dst + 8, src + 8); cp_async16(dst + 12, src + 12);
            asm volatile("cp.async.commit_group;");
        }

        u64 ar[8], az[8], an[8];
        #pragma unroll
        for (int rr = 0; rr < 8; rr++) { ar[rr] = br; az[rr] = bz; an[rr] = bn; }
        #pragma unroll 2
        for (int k = 0; k < 64; k++) {
            float4 k03 = *(const float4*)(kT + k * KT_S + r0);      // broadcast
            float4 k47 = *(const float4*)(kT + k * KT_S + r0 + 4);  // broadcast
            u64 wr = *(const u64*)(Wr + k * 66 + 2 * lane);
            u64 wz = *(const u64*)(Wz + k * 66 + 2 * lane);
            u64 wn = *(const u64*)(Wn + k * 66 + 2 * lane);
            float kv8[8] = {k03.x, k03.y, k03.z, k03.w, k47.x, k47.y, k47.z, k47.w};
            #pragma unroll
            for (int rr = 0; rr < 8; rr++) {
                u64 k2 = pk2(kv8[rr], kv8[rr]);
                fma2(ar[rr], k2, wr); fma2(az[rr], k2, wz); fma2(an[rr], k2, wn);
            }
        }
        #pragma unroll
        for (int rr = 0; rr < 8; rr++) {
            size_t row = row0 + tile * 32 + r0 + rr;
            *(u64*)(g_xp +            row * EE + 2 * lane) = ar[rr];
            *(u64*)(g_xp + RT64     + row * EE + 2 * lane) = az[rr];
            *(u64*)(g_xp + 2 * RT64 + row * EE + 2 * lane) = an[rr];
        }
    }
}

// =====================================================================
// Kernel 3: GRU scan (h@U only). 128 CTAs x 256 thr, 8 warps x 4 rows,
// hT transposed [e][row] stride 36.
// =====================================================================
#define HT_S 36
__global__ __launch_bounds__(256, 1) void scan_kernel(
    const float* __restrict__ U, float* __restrict__ out)
{
    extern __shared__ float sm[];
    float* Ur = sm;                 // [64][66] each
    float* Uz = Ur + 64 * 66;
    float* Un = Uz + 64 * 66;
    float* hT   = Un + 64 * 66;     // [64][36]
    float* attS = hT + 64 * HT_S;   // [2][32]

    int tid = threadIdx.x, lane = tid & 31, wid = tid >> 5;
    int rb  = blockIdx.x * 32;

    for (int i = tid; i < 64 * 64; i += 256) {
        int k = i >> 6, e = i & 63;
        const float* urow = U + k * 192;
        Ur[k * 66 + e] = urow[e];
        Uz[k * 66 + e] = urow[64 + e];
        Un[k * 66 + e] = urow[128 + e];
    }
    for (int i = tid; i < 64 * HT_S; i += 256) hT[i] = 0.0f;
    if (tid < 32) attS[tid] = g_att[(size_t)(rb + tid) * TT];
    __syncthreads();

    int r0 = wid * 4;
    float2 hreg[4];
    #pragma unroll
    for (int rr = 0; rr < 4; rr++) hreg[rr] = make_float2(0.0f, 0.0f);

    u64 xcr[4], xcz[4], xcn[4];
    #pragma unroll
    for (int rr = 0; rr < 4; rr++) {
        size_t row = ((size_t)(rb + r0 + rr) * TT) * EE + 2 * lane;   // t = 0
        xcr[rr] = *(const u64*)(g_xp + row);
        xcz[rr] = *(const u64*)(g_xp + RT64 + row);
        xcn[rr] = *(const u64*)(g_xp + 2 * RT64 + row);
    }

    for (int t = 0; t < TT; t++) {
        int cur = t & 1, nxt = cur ^ 1;

        u64 xnr[4], xnz[4], xnn[4];
        float aN = 0.0f;
        if (t + 1 < TT) {
            #pragma unroll
            for (int rr = 0; rr < 4; rr++) {
                size_t row = ((size_t)(rb + r0 + rr) * TT + (t + 1)) * EE + 2 * lane;
                xnr[rr] = *(const u64*)(g_xp + row);
                xnz[rr] = *(const u64*)(g_xp + RT64 + row);
                xnn[rr] = *(const u64*)(g_xp + 2 * RT64 + row);
            }
            if (tid < 32) aN = g_att[(size_t)(rb + tid) * TT + t + 1];
        }

        u64 a2r[4], a2z[4], a2n[4];
        #pragma unroll
        for (int rr = 0; rr < 4; rr++) { a2r[rr] = 0ull; a2z[rr] = 0ull; a2n[rr] = 0ull; }

        #pragma unroll 4
        for (int k = 0; k < 64; k++) {
            float4 h03 = *(const float4*)(hT + k * HT_S + r0);   // broadcast LDS.128
            u64 ur = *(const u64*)(Ur + k * 66 + 2 * lane);
            u64 uz = *(const u64*)(Uz + k * 66 + 2 * lane);
            u64 un = *(const u64*)(Un + k * 66 + 2 * lane);
            float hv4[4] = {h03.x, h03.y, h03.z, h03.w};
            #pragma unroll
            for (int rr = 0; rr < 4; rr++) {
                u64 h2 = pk2(hv4[rr], hv4[rr]);
                fma2(a2r[rr], h2, ur); fma2(a2z[rr], h2, uz); fma2(a2n[rr], h2, un);
            }
        }

        __syncthreads();   // all warps done reading hT of step t

        #pragma unroll
        for (int rr = 0; rr < 4; rr++) {
            int row = r0 + rr;
            float2 xr = up2(xcr[rr]), xz = up2(xcz[rr]), xn = up2(xcn[rr]);
            float2 hr = up2(a2r[rr]), hz = up2(a2z[rr]), hn = up2(a2n[rr]);
            float av = attS[cur * 32 + row];      // mask already folded
            float2 hold = hreg[rr];
            float2 rg = sigmoid2(xr.x + hr.x, xr.y + hr.y);
            float2 zg = sigmoid2(xz.x + hz.x, xz.y + hz.y);
            float2 ng = tanh2(xn.x + rg.x * hn.x, xn.y + rg.y * hn.y);
            float zt0 = av * zg.x, zt1 = av * zg.y;
            hreg[rr] = make_float2(hold.x + zt0 * (ng.x - hold.x),
                                   hold.y + zt1 * (ng.y - hold.y));
        }
        {   // transposed write: 2x STS.128
            float4 vx = make_float4(hreg[0].x, hreg[1].x, hreg[2].x, hreg[3].x);
            float4 vy = make_float4(hreg[0].y, hreg[1].y, hreg[2].y, hreg[3].y);
            *(float4*)(hT + (2 * lane)     * HT_S + r0) = vx;
            *(float4*)(hT + (2 * lane + 1) * HT_S + r0) = vy;
        }
        if (t + 1 < TT) {
            if (tid < 32) attS[nxt * 32 + tid] = aN;
            #pragma unroll
            for (int rr = 0; rr < 4; rr++) {
                xcr[rr] = xnr[rr]; xcz[rr] = xnz[rr]; xcn[rr] = xnn[rr];
            }
        }
        __syncthreads();   // hT/attS ready for step t+1
    }

    #pragma unroll
    for (int rr = 0; rr < 4; rr++) {
        int row = r0 + rr;
        *(float2*)(out + (size_t)(rb + row) * EE + 2 * lane) = hreg[rr];
    }
}

// =====================================================================
extern "C" void kernel_launch(void* const* d_in, const int* in_sizes, int n_in,
                              void* d_out, int out_size) {
    const float* gru   = (const float*)d_in[0];
    const float* query = (const float*)d_in[1];
    const void*  maskp = (const void*) d_in[2];
    const float* aw1   = (const float*)d_in[3];
    const float* ab1   = (const float*)d_in[4];
    const float* aw2   = (const float*)d_in[5];
    const float* ab2   = (const float*)d_in[6];
    const float* aw3   = (const float*)d_in[7];
    const float* ab3   = (const float*)d_in[8];
    const float* W     = (const float*)d_in[9];
    const float* U     = (const float*)d_in[10];
    const float* bias  = (const float*)d_in[11];
    float* out = (float*)d_out;

    const int attn_smem = (64 + 32 + 2048 + 2048 + 512 + 16 + 16 + 16 + TT * 65) * 4;
    const int xp_smem   = (3 * 64 * 66 + 32 * 68 + 64 * KT_S) * 4;
    const int scan_smem = (3 * 64 * 66 + 64 * HT_S + 64) * 4;
    cudaFuncSetAttribute(attn_kernel, cudaFuncAttributeMaxDynamicSharedMemorySize, attn_smem);
    cudaFuncSetAttribute(xp_kernel,   cudaFuncAttributeMaxDynamicSharedMemorySize, xp_smem);
    cudaFuncSetAttribute(scan_kernel, cudaFuncAttributeMaxDynamicSharedMemorySize, scan_smem);

    // One-time host-side resources (no device memory; work stays deterministic).
    static cudaStream_t sA = nullptr, sB = nullptr;
    static cudaEvent_t  evFork = nullptr, evA = nullptr, evB = nullptr;
    if (sA == nullptr) {
        cudaStreamCreateWithFlags(&sA, cudaStreamNonBlocking);
        cudaStreamCreateWithFlags(&sB, cudaStreamNonBlocking);
        cudaEventCreateWithFlags(&evFork, cudaEventDisableTiming);
        cudaEventCreateWithFlags(&evA,    cudaEventDisableTiming);
        cudaEventCreateWithFlags(&evB,    cudaEventDisableTiming);
    }

    // fork: attn (crossbar/MUFU-bound) || xp (FMA-bound) on separate streams
    cudaEventRecord(evFork, 0);
    cudaStreamWaitEvent(sA, evFork, 0);
    cudaStreamWaitEvent(sB, evFork, 0);
    attn_kernel<<<BB, 256, attn_smem, sA>>>(gru, query, maskp,
                                            aw1, ab1, aw2, ab2, aw3, ab3);
    xp_kernel<<<(BB * TT) / XP_RPB, 128, xp_smem, sB>>>(gru, W, bias);
    cudaEventRecord(evA, sA);
    cudaEventRecord(evB, sB);
    cudaStreamWaitEvent(0, evA, 0);
    cudaStreamWaitEvent(0, evB, 0);

    // join: scan consumes g_att + g_xp
    scan_kernel<<<128, 256, scan_smem>>>(U, out);
}

// round 12
// speedup vs baseline: 1.3228x; 1.0855x over previous
#include <cuda_runtime.h>
#include <cuda_bf16.h>
#include <cstdint>
#include <math.h>

#define BB 4096
#define TT 200
#define EE 64

using u64 = unsigned long long;

// ---------------- device globals ----------------
__device__ float g_att[(size_t)BB * TT];            // softmax * mask, [B,T]
__device__ float g_xp[3ull * BB * TT * EE];         // xp = gru@W + b, [gate][b*T+t][e]
#define RT64 ((size_t)BB * TT * EE)

// ---------------- packed fp32x2 helpers ----------------
static __device__ __forceinline__ u64 pk2(float x, float y) {
    u64 r; asm("mov.b64 %0,{%1,%2};" : "=l"(r) : "f"(x), "f"(y)); return r;
}
static __device__ __forceinline__ float2 up2(u64 v) {
    float2 r; asm("mov.b64 {%0,%1},%2;" : "=f"(r.x), "=f"(r.y) : "l"(v)); return r;
}
static __device__ __forceinline__ void fma2(u64& d, u64 a, u64 b) {
    asm("fma.rn.f32x2 %0,%1,%2,%0;" : "+l"(d) : "l"(a), "l"(b));
}
static __device__ __forceinline__ float rcpa(float x) {
    float r; asm("rcp.approx.f32 %0, %1;" : "=f"(r) : "f"(x)); return r;
}
// two sigmoids sharing one MUFU.RCP (validated: rel_err 3.3e-7)
static __device__ __forceinline__ float2 sigmoid2(float a, float b) {
    float ea = __expf(-fabsf(a)), eb = __expf(-fabsf(b));
    float pa = 1.0f + ea, pb = 1.0f + eb;
    float R  = rcpa(pa * pb);
    float ia = pb * R, ib = pa * R;
    float sa = (a >= 0.0f) ? ia : ea * ia;
    float sb = (b >= 0.0f) ? ib : eb * ib;
    return make_float2(sa, sb);
}
// two tanhs sharing one MUFU.RCP (validated)
static __device__ __forceinline__ float2 tanh2(float a, float b) {
    float ea = __expf(-2.0f * fabsf(a)), eb = __expf(-2.0f * fabsf(b));
    float pa = 1.0f + ea, pb = 1.0f + eb;
    float R  = rcpa(pa * pb);
    float ta = (1.0f - ea) * pb * R, tb = (1.0f - eb) * pa * R;
    return make_float2(copysignf(ta, a), copysignf(tb, b));
}
static __device__ __forceinline__ void cp_async16(void* dst, const void* src) {
    unsigned s = (unsigned)__cvta_generic_to_shared(dst);
    asm volatile("cp.async.cg.shared.global [%0], [%1], 16;" :: "r"(s), "l"(src));
}
static __device__ __forceinline__ int load_mask(const void* mp, size_t idx, int u8) {
    return u8 ? (int)(((const unsigned char*)mp)[idx] != 0)
              : (int)(((const int*)mp)[idx] != 0);
}

// =====================================================================
// Kernel 1: attention + softmax, one CTA per b, 128 threads.
// Each thread computes TWO t-values (t, t+128) sharing one set of
// broadcast weight loads -> weight crossbar wavefronts per logit halved.
// =====================================================================
__global__ __launch_bounds__(128, 3) void attn_kernel(
    const float* __restrict__ gru, const float* __restrict__ query,
    const void* __restrict__ maskp,
    const float* __restrict__ aw1, const float* __restrict__ ab1,
    const float* __restrict__ aw2, const float* __restrict__ ab2,
    const float* __restrict__ aw3, const float* __restrict__ ab3)
{
    extern __shared__ float sm[];
    float* q_s   = sm;              // 64
    float* qa_s  = sm + 64;         // 32
    float* Wk_s  = sm + 96;         // 64*32 = A1 - A2
    float* Wqk_s = Wk_s + 2048;     // 64*32 = A3
    float* aw2_s = Wqk_s + 2048;    // 512
    float* ab2_s = aw2_s + 512;     // 16
    float* aw3_s = ab2_s + 16;      // 16
    float* red_s = aw3_s + 16;      // 16 (warp partials, bmax@8, sum@9, flag@12)
    float* Ks    = red_s + 16;      // 200*65

    int tid = threadIdx.x;
    int b   = blockIdx.x;

    if (tid < 32) {   // warp-parallel mask dtype detection
        const unsigned int* mw = (const unsigned int*)maskp;
        unsigned bad = 0;
        #pragma unroll
        for (int i = 0; i < 16; i++) bad |= (mw[tid * 16 + i] > 1u) ? 1u : 0u;
        unsigned any = __any_sync(0xffffffffu, bad);
        if (tid == 0) red_s[12] = any ? 1.0f : 0.0f;
    }

    if (tid < 64) q_s[tid] = query[(size_t)b * EE + tid];
    for (int i = tid; i < 2048; i += 128) {
        int e = i >> 5, j = i & 31;
        Wk_s[i]  = aw1[(64 + e) * 32 + j] - aw1[(128 + e) * 32 + j];
        Wqk_s[i] = aw1[(192 + e) * 32 + j];
    }
    for (int i = tid; i < 512; i += 128) aw2_s[i] = aw2[i];
    if (tid < 16) { ab2_s[tid] = ab2[tid]; aw3_s[tid] = aw3[tid]; }
    for (int i = tid; i < TT * 16; i += 128) {
        int row = i >> 4, c = (i & 15) * 4;
        float4 v = *(const float4*)(gru + ((size_t)b * TT + row) * EE + c);
        float* d = Ks + row * 65 + c;
        d[0] = v.x; d[1] = v.y; d[2] = v.z; d[3] = v.w;
    }
    __syncthreads();

    if (tid < 32) {
        float s = ab1[tid];
        for (int e = 0; e < 64; e++)
            s += q_s[e] * (aw1[e * 32 + tid] + aw1[(128 + e) * 32 + tid]);
        qa_s[tid] = s;
    }
    __syncthreads();

    int mu8 = (red_s[12] != 0.0f);
    int t0 = tid;                 // always < 200
    int t1 = tid + 128;
    bool v1 = (t1 < TT);
    int t1r = v1 ? t1 : t0;       // clamp for safe smem reads

    // ---- MLP1 for both t's, shared weight loads ----
    u64 acc0[16], acc1[16];
    const ulonglong2* Wk4  = (const ulonglong2*)Wk_s;
    const ulonglong2* Wqk4 = (const ulonglong2*)Wqk_s;
    #pragma unroll
    for (int j = 0; j < 16; j++) {
        u64 qa = pk2(qa_s[2 * j], qa_s[2 * j + 1]);
        acc0[j] = qa; acc1[j] = qa;
    }
    const float* kr0 = Ks + t0 * 65;
    const float* kr1 = Ks + t1r * 65;
    #pragma unroll 4
    for (int e = 0; e < 64; e++) {
        float qv  = q_s[e];
        float kv0 = kr0[e], kv1 = kr1[e];
        u64 k20 = pk2(kv0, kv0), q20 = pk2(qv * kv0, qv * kv0);
        u64 k21 = pk2(kv1, kv1), q21 = pk2(qv * kv1, qv * kv1);
        #pragma unroll
        for (int j2 = 0; j2 < 8; j2++) {
            ulonglong2 wa = Wk4[e * 8 + j2];      // shared by both t's
            ulonglong2 wb = Wqk4[e * 8 + j2];
            fma2(acc0[2 * j2],     k20, wa.x); fma2(acc0[2 * j2 + 1], k20, wa.y);
            fma2(acc0[2 * j2],     q20, wb.x); fma2(acc0[2 * j2 + 1], q20, wb.y);
            fma2(acc1[2 * j2],     k21, wa.x); fma2(acc1[2 * j2 + 1], k21, wa.y);
            fma2(acc1[2 * j2],     q21, wb.x); fma2(acc1[2 * j2 + 1], q21, wb.y);
        }
    }

    // ---- MLP2 + logit, per t ----
    const ulonglong2* A24 = (const ulonglong2*)aw2_s;
    float lgt[2];
    #pragma unroll
    for (int which = 0; which < 2; which++) {
        u64* acc = which ? acc1 : acc0;
        u64 acc2[8];
        #pragma unroll
        for (int j = 0; j < 8; j++) acc2[j] = pk2(ab2_s[2 * j], ab2_s[2 * j + 1]);
        #pragma unroll
        for (int j = 0; j < 16; j++) {
            float2 v = up2(acc[j]);
            float2 h = sigmoid2(v.x, v.y);
            u64 ha = pk2(h.x, h.x), hb = pk2(h.y, h.y);
            #pragma unroll
            for (int j2 = 0; j2 < 4; j2++) {
                ulonglong2 wa = A24[(2 * j) * 4 + j2];
                fma2(acc2[2 * j2],     ha, wa.x);
                fma2(acc2[2 * j2 + 1], ha, wa.y);
                ulonglong2 wb = A24[(2 * j + 1) * 4 + j2];
                fma2(acc2[2 * j2],     hb, wb.x);
                fma2(acc2[2 * j2 + 1], hb, wb.y);
            }
        }
        float l = ab3[0];
        #pragma unroll
        for (int j = 0; j < 8; j++) {
            float2 v = up2(acc2[j]);
            float2 h = sigmoid2(v.x, v.y);
            l += h.x * aw3_s[2 * j] + h.y * aw3_s[2 * j + 1];
        }
        lgt[which] = l;
    }

    int m0 = load_mask(maskp, (size_t)b * TT + t0, mu8);
    int m1 = v1 ? load_mask(maskp, (size_t)b * TT + t1, mu8) : 0;
    float lg0 = m0 ? lgt[0] : -1.0e9f;
    float lg1 = v1 ? (m1 ? lgt[1] : -1.0e9f) : -3.0e38f;

    // ---- block softmax over 200 logits (128 threads, 4 warps) ----
    float v = fmaxf(lg0, lg1);
    #pragma unroll
    for (int off = 16; off > 0; off >>= 1) v = fmaxf(v, __shfl_xor_sync(0xffffffffu, v, off));
    if ((tid & 31) == 0) red_s[tid >> 5] = v;
    __syncthreads();
    if (tid == 0) { float m = red_s[0]; for (int i = 1; i < 4; i++) m = fmaxf(m, red_s[i]); red_s[8] = m; }
    __syncthreads();
    float bmax = red_s[8];
    float ex0 = __expf(lg0 - bmax);
    float ex1 = v1 ? __expf(lg1 - bmax) : 0.0f;
    float s = ex0 + ex1;
    #pragma unroll
    for (int off = 16; off > 0; off >>= 1) s += __shfl_xor_sync(0xffffffffu, s, off);
    if ((tid & 31) == 0) red_s[tid >> 5] = s;
    __syncthreads();
    if (tid == 0) { float m = 0.0f; for (int i = 0; i < 4; i++) m += red_s[i]; red_s[9] = m; }
    __syncthreads();
    float inv = __frcp_rn(red_s[9]);
    g_att[(size_t)b * TT + t0] = ex0 * inv * (m0 ? 1.0f : 0.0f);
    if (v1) g_att[(size_t)b * TT + t1] = ex1 * inv * (m1 ? 1.0f : 0.0f);
}

// =====================================================================
// Kernel 2: xp = gru@W + b (gate-split). 128 thr, 8 tiles of 32 rows.
// k-tiles transposed into kT so activation reads are broadcast LDS.128.
// =====================================================================
#define XP_RPB 256
#define KT_S 36
__global__ __launch_bounds__(128) void xp_kernel(
    const float* __restrict__ gru, const float* __restrict__ W,
    const float* __restrict__ bias)
{
    extern __shared__ float sm[];
    float* Wr = sm;                 // [64][66] each
    float* Wz = Wr + 64 * 66;
    float* Wn = Wz + 64 * 66;
    float* stage = Wn + 64 * 66;    // [32][68] cp.async target
    float* kT    = stage + 32 * 68; // [64][36] transposed tile

    int tid = threadIdx.x, lane = tid & 31, wid = tid >> 5;
    size_t row0 = (size_t)blockIdx.x * XP_RPB;

    for (int i = tid; i < 64 * 64; i += 128) {
        int k = i >> 6, e = i & 63;
        const float* wrow = W + k * 192;
        Wr[k * 66 + e] = wrow[e];
        Wz[k * 66 + e] = wrow[64 + e];
        Wn[k * 66 + e] = wrow[128 + e];
    }

    int r = tid >> 2, c0 = (tid & 3) * 16;
    {   // preload tile 0 -> stage
        const float* src = gru + (row0 + r) * EE + c0;
        float* dst = stage + r * 68 + c0;
        cp_async16(dst, src);      cp_async16(dst + 4, src + 4);
        cp_async16(dst + 8, src + 8); cp_async16(dst + 12, src + 12);
        asm volatile("cp.async.commit_group;");
    }

    u64 br = *(const u64*)(bias + 2 * lane);
    u64 bz = *(const u64*)(bias + 64 + 2 * lane);
    u64 bn = *(const u64*)(bias + 128 + 2 * lane);
    int r0 = wid * 8;

    for (int tile = 0; tile < XP_RPB / 32; tile++) {
        asm volatile("cp.async.wait_group 0;" ::: "memory");
        __syncthreads();           // stage holds tile

        {   // transpose stage -> kT
            const float* srow = stage + r * 68 + c0;
            #pragma unroll
            for (int q = 0; q < 4; q++) {
                float4 v = *(const float4*)(srow + 4 * q);
                kT[(c0 + 4 * q + 0) * KT_S + r] = v.x;
                kT[(c0 + 4 * q + 1) * KT_S + r] = v.y;
                kT[(c0 + 4 * q + 2) * KT_S + r] = v.z;
                kT[(c0 + 4 * q + 3) * KT_S + r] = v.w;
            }
        }
        __syncthreads();           // kT ready; stage free

        if (tile + 1 < XP_RPB / 32) {
            const float* src = gru + (row0 + (tile + 1) * 32 + r) * EE + c0;
            float* dst = stage + r * 68 + c0;
            cp_async16(dst, src);      cp_async16(dst + 4, src + 4);
            cp_async16(dst + 8, src + 8); cp_async16(dst + 12, src + 12);
            asm volatile("cp.async.commit_group;");
        }

        u64 ar[8], az[8], an[8];
        #pragma unroll
        for (int rr = 0; rr < 8; rr++) { ar[rr] = br; az[rr] = bz; an[rr] = bn; }
        #pragma unroll 2
        for (int k = 0; k < 64; k++) {
            float4 k03 = *(const float4*)(kT + k * KT_S + r0);      // broadcast
            float4 k47 = *(const float4*)(kT + k * KT_S + r0 + 4);  // broadcast
            u64 wr = *(const u64*)(Wr + k * 66 + 2 * lane);
            u64 wz = *(const u64*)(Wz + k * 66 + 2 * lane);
            u64 wn = *(const u64*)(Wn + k * 66 + 2 * lane);
            float kv8[8] = {k03.x, k03.y, k03.z, k03.w, k47.x, k47.y, k47.z, k47.w};
            #pragma unroll
            for (int rr = 0; rr < 8; rr++) {
                u64 k2 = pk2(kv8[rr], kv8[rr]);
                fma2(ar[rr], k2, wr); fma2(az[rr], k2, wz); fma2(an[rr], k2, wn);
            }
        }
        #pragma unroll
        for (int rr = 0; rr < 8; rr++) {
            size_t row = row0 + tile * 32 + r0 + rr;
            *(u64*)(g_xp +            row * EE + 2 * lane) = ar[rr];
            *(u64*)(g_xp + RT64     + row * EE + 2 * lane) = az[rr];
            *(u64*)(g_xp + 2 * RT64 + row * EE + 2 * lane) = an[rr];
        }
    }
}

// =====================================================================
// Kernel 3: GRU scan (h@U only). 128 CTAs x 256 thr, 8 warps x 4 rows.
// hT DOUBLE-BUFFERED -> one __syncthreads per step (k-loop reads
// hT[cur] while epilogue writes hT[nxt]; no intra-step hazard).
// =====================================================================
#define HT_S 36
__global__ __launch_bounds__(256, 1) void scan_kernel(
    const float* __restrict__ U, float* __restrict__ out)
{
    extern __shared__ float sm[];
    float* Ur = sm;                 // [64][66] each
    float* Uz = Ur + 64 * 66;
    float* Un = Uz + 64 * 66;
    float* hT   = Un + 64 * 66;     // [2][64][36]
    float* attS = hT + 2 * 64 * HT_S; // [2][32]

    int tid = threadIdx.x, lane = tid & 31, wid = tid >> 5;
    int rb  = blockIdx.x * 32;

    for (int i = tid; i < 64 * 64; i += 256) {
        int k = i >> 6, e = i & 63;
        const float* urow = U + k * 192;
        Ur[k * 66 + e] = urow[e];
        Uz[k * 66 + e] = urow[64 + e];
        Un[k * 66 + e] = urow[128 + e];
    }
    for (int i = tid; i < 64 * HT_S; i += 256) hT[i] = 0.0f;   // buffer 0 only
    if (tid < 32) attS[tid] = g_att[(size_t)(rb + tid) * TT];
    __syncthreads();

    int r0 = wid * 4;
    float2 hreg[4];
    #pragma unroll
    for (int rr = 0; rr < 4; rr++) hreg[rr] = make_float2(0.0f, 0.0f);

    u64 xcr[4], xcz[4], xcn[4];
    #pragma unroll
    for (int rr = 0; rr < 4; rr++) {
        size_t row = ((size_t)(rb + r0 + rr) * TT) * EE + 2 * lane;   // t = 0
        xcr[rr] = *(const u64*)(g_xp + row);
        xcz[rr] = *(const u64*)(g_xp + RT64 + row);
        xcn[rr] = *(const u64*)(g_xp + 2 * RT64 + row);
    }

    for (int t = 0; t < TT; t++) {
        int cur = t & 1, nxt = cur ^ 1;
        const float* hc = hT + cur * 64 * HT_S;
        float*       hn_ = hT + nxt * 64 * HT_S;

        u64 xnr[4], xnz[4], xnn[4];
        float aN = 0.0f;
        if (t + 1 < TT) {
            #pragma unroll
            for (int rr = 0; rr < 4; rr++) {
                size_t row = ((size_t)(rb + r0 + rr) * TT + (t + 1)) * EE + 2 * lane;
                xnr[rr] = *(const u64*)(g_xp + row);
                xnz[rr] = *(const u64*)(g_xp + RT64 + row);
                xnn[rr] = *(const u64*)(g_xp + 2 * RT64 + row);
            }
            if (tid < 32) aN = g_att[(size_t)(rb + tid) * TT + t + 1];
        }

        u64 a2r[4], a2z[4], a2n[4];
        #pragma unroll
        for (int rr = 0; rr < 4; rr++) { a2r[rr] = 0ull; a2z[rr] = 0ull; a2n[rr] = 0ull; }

        #pragma unroll 4
        for (int k = 0; k < 64; k++) {
            float4 h03 = *(const float4*)(hc + k * HT_S + r0);   // broadcast LDS.128
            u64 ur = *(const u64*)(Ur + k * 66 + 2 * lane);
            u64 uz = *(const u64*)(Uz + k * 66 + 2 * lane);
            u64 un = *(const u64*)(Un + k * 66 + 2 * lane);
            float hv4[4] = {h03.x, h03.y, h03.z, h03.w};
            #pragma unroll
            for (int rr = 0; rr < 4; rr++) {
                u64 h2 = pk2(hv4[rr], hv4[rr]);
                fma2(a2r[rr], h2, ur); fma2(a2z[rr], h2, uz); fma2(a2n[rr], h2, un);
            }
        }

        #pragma unroll
        for (int rr = 0; rr < 4; rr++) {
            int row = r0 + rr;
            float2 xr = up2(xcr[rr]), xz = up2(xcz[rr]), xn = up2(xcn[rr]);
            float2 hr = up2(a2r[rr]), hz = up2(a2z[rr]), hn = up2(a2n[rr]);
            float av = attS[cur * 32 + row];      // mask already folded
            float2 hold = hreg[rr];
            float2 rg = sigmoid2(xr.x + hr.x, xr.y + hr.y);
            float2 zg = sigmoid2(xz.x + hz.x, xz.y + hz.y);
            float2 ng = tanh2(xn.x + rg.x * hn.x, xn.y + rg.y * hn.y);
            float zt0 = av * zg.x, zt1 = av * zg.y;
            hreg[rr] = make_float2(hold.x + zt0 * (ng.x - hold.x),
                                   hold.y + zt1 * (ng.y - hold.y));
        }
        {   // transposed write to the OTHER buffer: 2x STS.128
            float4 vx = make_float4(hreg[0].x, hreg[1].x, hreg[2].x, hreg[3].x);
            float4 vy = make_float4(hreg[0].y, hreg[1].y, hreg[2].y, hreg[3].y);
            *(float4*)(hn_ + (2 * lane)     * HT_S + r0) = vx;
            *(float4*)(hn_ + (2 * lane + 1) * HT_S + r0) = vy;
        }
        if (t + 1 < TT) {
            if (tid < 32) attS[nxt * 32 + tid] = aN;
            #pragma unroll
            for (int rr = 0; rr < 4; rr++) {
                xcr[rr] = xnr[rr]; xcz[rr] = xnz[rr]; xcn[rr] = xnn[rr];
            }
        }
        __syncthreads();   // single barrier: hT[nxt]/attS[nxt] ready for t+1
    }

    #pragma unroll
    for (int rr = 0; rr < 4; rr++) {
        int row = r0 + rr;
        *(float2*)(out + (size_t)(rb + row) * EE + 2 * lane) = hreg[rr];
    }
}

// =====================================================================
extern "C" void kernel_launch(void* const* d_in, const int* in_sizes, int n_in,
                              void* d_out, int out_size) {
    const float* gru   = (const float*)d_in[0];
    const float* query = (const float*)d_in[1];
    const void*  maskp = (const void*) d_in[2];
    const float* aw1   = (const float*)d_in[3];
    const float* ab1   = (const float*)d_in[4];
    const float* aw2   = (const float*)d_in[5];
    const float* ab2   = (const float*)d_in[6];
    const float* aw3   = (const float*)d_in[7];
    const float* ab3   = (const float*)d_in[8];
    const float* W     = (const float*)d_in[9];
    const float* U     = (const float*)d_in[10];
    const float* bias  = (const float*)d_in[11];
    float* out = (float*)d_out;

    const int attn_smem = (64 + 32 + 2048 + 2048 + 512 + 16 + 16 + 16 + TT * 65) * 4;
    const int xp_smem   = (3 * 64 * 66 + 32 * 68 + 64 * KT_S) * 4;
    const int scan_smem = (3 * 64 * 66 + 2 * 64 * HT_S + 64) * 4;
    cudaFuncSetAttribute(attn_kernel, cudaFuncAttributeMaxDynamicSharedMemorySize, attn_smem);
    cudaFuncSetAttribute(xp_kernel,   cudaFuncAttributeMaxDynamicSharedMemorySize, xp_smem);
    cudaFuncSetAttribute(scan_kernel, cudaFuncAttributeMaxDynamicSharedMemorySize, scan_smem);

    attn_kernel<<<BB, 128, attn_smem>>>(gru, query, maskp, aw1, ab1, aw2, ab2, aw3, ab3);
    xp_kernel<<<(BB * TT) / XP_RPB, 128, xp_smem>>>(gru, W, bias);
    scan_kernel<<<128, 256, scan_smem>>>(U, out);
}